// round 2
// baseline (speedup 1.0000x reference)
#include <cuda_runtime.h>
#include <cstdint>

// Problem shape (fixed by the dataset)
constexpr int B_N    = 256;
constexpr int T_N    = 16384;
constexpr int CHUNKS = 8;                      // chunks per sample -> 2048 blocks
constexpr int TPB    = 256;
constexpr int CHUNK_ELEMS = T_N / CHUNKS;      // 2048 elems per block
constexpr int QUADS_PER_THREAD = CHUNK_ELEMS / 4 / TPB;  // 2
constexpr int NBLOCKS = B_N * CHUNKS;          // 2048

constexpr float EPS_C    = 1e-4f;
// SR / (T * TARGET_FACTOR) = 22050 / (16384*256)
constexpr float INV_CLIP = 22050.0f / (16384.0f * 256.0f);

// Per-(sample,chunk) partials: {cls_sum, num_pos, reg_sum, K}
__device__ float g_partial[NBLOCKS * 4];
__device__ unsigned int g_ticket;  // zero-init; reset by final block each run

__device__ __forceinline__ float cls_term(float c, bool lab) {
    c = fminf(fmaxf(c, EPS_C), 1.0f - EPS_C);
    // lab: 0.25*(1-c)^5 * -log(c) ; else: 0.75*c^5 * -log(1-c)
    const float p  = lab ? (1.0f - c) : c;
    const float lg = lab ? __logf(c) : __logf(1.0f - c);
    const float a  = lab ? 0.25f : 0.75f;
    const float p2 = p * p;
    return a * (p2 * p2 * p) * (-lg);
}

__global__ __launch_bounds__(TPB) void fused_kernel(
    const float* __restrict__ cls,   // [B, T, 2]
    const float* __restrict__ reg,   // [B, T, 1]
    const float* __restrict__ ann,   // [B, 3, T]
    float* __restrict__ out)         // [2]
{
    const int b     = blockIdx.y;
    const int chunk = blockIdx.x;
    const int tbase = chunk * CHUNK_ELEMS;

    const float* __restrict__ ann0 = ann + (size_t)b * 3 * T_N;
    const float* __restrict__ ann1 = ann0 + T_N;
    const float* __restrict__ ann2 = ann0 + 2 * T_N;
    const float* __restrict__ clsb = cls + (size_t)b * T_N * 2;
    const float* __restrict__ regb = reg + (size_t)b * T_N;

    float cls_sum = 0.0f;
    float reg_sum = 0.0f;
    int   np = 0;   // num_pos: original beat mask count (classification normalizer)
    int   K  = 0;   // fixed-pos count (regression normalizer)

    #pragma unroll
    for (int j = 0; j < QUADS_PER_THREAD; ++j) {
        const int q = threadIdx.x + j * TPB;   // quad index within chunk
        const int t = tbase + q * 4;

        const float4 a0 = *reinterpret_cast<const float4*>(ann0 + t);
        const float4 a1 = *reinterpret_cast<const float4*>(ann1 + t);
        const float4 a2 = *reinterpret_cast<const float4*>(ann2 + t);
        const float4 cA = *reinterpret_cast<const float4*>(clsb + 2 * t);
        const float4 cB = *reinterpret_cast<const float4*>(clsb + 2 * t + 4);
        const float4 r  = *reinterpret_cast<const float4*>(regb + t);

        const float a0v[4] = {a0.x, a0.y, a0.z, a0.w};
        const float a1v[4] = {a1.x, a1.y, a1.z, a1.w};
        const float a2v[4] = {a2.x, a2.y, a2.z, a2.w};
        const float cv[8]  = {cA.x, cA.y, cA.z, cA.w, cB.x, cB.y, cB.z, cB.w};
        const float rv[4]  = {r.x,  r.y,  r.z,  r.w};

        const bool last_quad = (t + 4 == T_N);

        #pragma unroll
        for (int e = 0; e < 4; ++e) {
            const bool beat = (a0v[e] != 0.0f);
            const bool down = (a1v[e] != 0.0f);
            np += beat ? 1 : 0;
            cls_sum += cls_term(cv[2 * e],     beat && down);
            cls_sum += cls_term(cv[2 * e + 1], beat && !down);

            // regression anchor mask with end-fix:
            //   pos[T-2] |= ann0[T-1];  pos[T-1] = 0
            bool pos = beat;
            if (last_quad) {
                if (e == 2) pos = beat || (a0v[3] != 0.0f);
                if (e == 3) pos = false;
            }
            if (pos) {
                ++K;
                const float rn    = a2v[e] * INV_CLIP;
                const float rnext = (e < 3) ? rv[e + 1] : __ldg(regb + t + 4);
                const float dl = rn - rv[e];
                const float dr = rn - rnext;
                reg_sum += 0.5f * (dl * dl + dr * dr);
            }
        }
    }

    // Block reduce four values (np/K as float)
    float v0 = cls_sum, v1 = (float)np, v2 = reg_sum, v3 = (float)K;
    #pragma unroll
    for (int o = 16; o > 0; o >>= 1) {
        v0 += __shfl_down_sync(0xFFFFFFFFu, v0, o);
        v1 += __shfl_down_sync(0xFFFFFFFFu, v1, o);
        v2 += __shfl_down_sync(0xFFFFFFFFu, v2, o);
        v3 += __shfl_down_sync(0xFFFFFFFFu, v3, o);
    }
    __shared__ float sm[4][TPB / 32];
    __shared__ unsigned int s_ticket;
    const int warp = threadIdx.x >> 5;
    const int lane = threadIdx.x & 31;
    if (lane == 0) {
        sm[0][warp] = v0; sm[1][warp] = v1; sm[2][warp] = v2; sm[3][warp] = v3;
    }
    __syncthreads();
    if (threadIdx.x == 0) {
        float s0 = 0.f, s1 = 0.f, s2 = 0.f, s3 = 0.f;
        #pragma unroll
        for (int w = 0; w < TPB / 32; ++w) {
            s0 += sm[0][w]; s1 += sm[1][w]; s2 += sm[2][w]; s3 += sm[3][w];
        }
        float* dst = &g_partial[((size_t)b * CHUNKS + chunk) * 4];
        dst[0] = s0; dst[1] = s1; dst[2] = s2; dst[3] = s3;
        __threadfence();                       // partials visible before ticket
        s_ticket = atomicAdd(&g_ticket, 1u);
    }
    __syncthreads();

    if (s_ticket != NBLOCKS - 1) return;

    // ---- Final reduction: this is the last block; all partials are in L2 ----
    {
        const int sb = threadIdx.x;            // sample index, 0..255
        float sc = 0.f, sn = 0.f, sr = 0.f, sk = 0.f;
        #pragma unroll
        for (int ch = 0; ch < CHUNKS; ++ch) {
            const float* p = &g_partial[((size_t)sb * CHUNKS + ch) * 4];
            sc += __ldcg(p + 0);
            sn += __ldcg(p + 1);
            sr += __ldcg(p + 2);
            sk += __ldcg(p + 3);
        }
        float cls_loss = sc / sn * 10.0f;
        float reg_loss = sr / sk * 10.0f;

        #pragma unroll
        for (int o = 16; o > 0; o >>= 1) {
            cls_loss += __shfl_down_sync(0xFFFFFFFFu, cls_loss, o);
            reg_loss += __shfl_down_sync(0xFFFFFFFFu, reg_loss, o);
        }
        __shared__ float sA[TPB / 32], sB[TPB / 32];
        if (lane == 0) { sA[warp] = cls_loss; sB[warp] = reg_loss; }
        __syncthreads();
        if (threadIdx.x == 0) {
            float tc = 0.f, tr = 0.f;
            #pragma unroll
            for (int w = 0; w < TPB / 32; ++w) { tc += sA[w]; tr += sB[w]; }
            out[0] = tc * (1.0f / (float)B_N);
            out[1] = tr * (1.0f / (float)B_N);
            g_ticket = 0u;                     // reset for next graph replay
        }
    }
}

extern "C" void kernel_launch(void* const* d_in, const int* in_sizes, int n_in,
                              void* d_out, int out_size) {
    const float* cls = (const float*)d_in[0];  // [B, T, 2]
    const float* reg = (const float*)d_in[1];  // [B, T, 1]
    const float* ann = (const float*)d_in[2];  // [B, 3, T]
    float* out = (float*)d_out;                // [2]

    dim3 grid(CHUNKS, B_N);
    fused_kernel<<<grid, TPB>>>(cls, reg, ann, out);
}

// round 3
// speedup vs baseline: 1.0084x; 1.0084x over previous
#include <cuda_runtime.h>
#include <cstdint>

// Problem shape (fixed by the dataset)
constexpr int B_N    = 256;
constexpr int T_N    = 16384;
constexpr int CHUNKS = 8;                      // chunks per sample -> 2048 blocks
constexpr int TPB    = 256;
constexpr int CHUNK_ELEMS = T_N / CHUNKS;      // 2048 elems per block
constexpr int QUADS_PER_THREAD = CHUNK_ELEMS / 4 / TPB;  // 2
constexpr int NBLOCKS = B_N * CHUNKS;          // 2048

constexpr float EPS_C    = 1e-4f;
// SR / (T * TARGET_FACTOR) = 22050 / (16384*256)
constexpr float INV_CLIP = 22050.0f / (16384.0f * 256.0f);

// Per-(sample,chunk) partials: {cls_sum, num_pos, reg_sum, K}
__device__ float g_partial[NBLOCKS * 4];
__device__ unsigned int g_ticket;  // zero-init; reset by final block each run

__device__ __forceinline__ float cls_term(float c, bool lab) {
    c = fminf(fmaxf(c, EPS_C), 1.0f - EPS_C);
    // lab: 0.25*(1-c)^5 * -log(c) ; else: 0.75*c^5 * -log(1-c)
    const float p  = lab ? (1.0f - c) : c;
    const float lg = lab ? __logf(c) : __logf(1.0f - c);
    const float a  = lab ? 0.25f : 0.75f;
    const float p2 = p * p;
    return a * (p2 * p2 * p) * (-lg);
}

// acq_rel ticket: release makes prior __stcg stores visible before the
// increment; acquire orders the winner's subsequent __ldcg reads.
// Crucially this does NOT emit CCTL.IVALL (no L1D flush), unlike
// __threadfence() which is gpu-scope and nukes L1 for co-resident blocks.
__device__ __forceinline__ unsigned int ticket_acq_rel(unsigned int* p) {
    unsigned int old;
    asm volatile("atom.acq_rel.gpu.global.add.u32 %0, [%1], 1;"
                 : "=r"(old) : "l"(p) : "memory");
    return old;
}

__global__ __launch_bounds__(TPB) void fused_kernel(
    const float* __restrict__ cls,   // [B, T, 2]
    const float* __restrict__ reg,   // [B, T, 1]
    const float* __restrict__ ann,   // [B, 3, T]
    float* __restrict__ out)         // [2]
{
    const int b     = blockIdx.y;
    const int chunk = blockIdx.x;
    const int tbase = chunk * CHUNK_ELEMS;

    const float* __restrict__ ann0 = ann + (size_t)b * 3 * T_N;
    const float* __restrict__ ann1 = ann0 + T_N;
    const float* __restrict__ ann2 = ann0 + 2 * T_N;
    const float* __restrict__ clsb = cls + (size_t)b * T_N * 2;
    const float* __restrict__ regb = reg + (size_t)b * T_N;

    float cls_sum = 0.0f;
    float reg_sum = 0.0f;
    int   np = 0;   // num_pos: original beat mask count (classification normalizer)
    int   K  = 0;   // fixed-pos count (regression normalizer)

    #pragma unroll
    for (int j = 0; j < QUADS_PER_THREAD; ++j) {
        const int q = threadIdx.x + j * TPB;   // quad index within chunk
        const int t = tbase + q * 4;

        const float4 a0 = *reinterpret_cast<const float4*>(ann0 + t);
        const float4 a1 = *reinterpret_cast<const float4*>(ann1 + t);
        const float4 a2 = *reinterpret_cast<const float4*>(ann2 + t);
        const float4 cA = *reinterpret_cast<const float4*>(clsb + 2 * t);
        const float4 cB = *reinterpret_cast<const float4*>(clsb + 2 * t + 4);
        const float4 r  = *reinterpret_cast<const float4*>(regb + t);

        const float a0v[4] = {a0.x, a0.y, a0.z, a0.w};
        const float a1v[4] = {a1.x, a1.y, a1.z, a1.w};
        const float a2v[4] = {a2.x, a2.y, a2.z, a2.w};
        const float cv[8]  = {cA.x, cA.y, cA.z, cA.w, cB.x, cB.y, cB.z, cB.w};
        const float rv[4]  = {r.x,  r.y,  r.z,  r.w};

        const bool last_quad = (t + 4 == T_N);

        #pragma unroll
        for (int e = 0; e < 4; ++e) {
            const bool beat = (a0v[e] != 0.0f);
            const bool down = (a1v[e] != 0.0f);
            np += beat ? 1 : 0;
            cls_sum += cls_term(cv[2 * e],     beat && down);
            cls_sum += cls_term(cv[2 * e + 1], beat && !down);

            // regression anchor mask with end-fix:
            //   pos[T-2] |= ann0[T-1];  pos[T-1] = 0
            bool pos = beat;
            if (last_quad) {
                if (e == 2) pos = beat || (a0v[3] != 0.0f);
                if (e == 3) pos = false;
            }
            if (pos) {
                ++K;
                const float rn    = a2v[e] * INV_CLIP;
                const float rnext = (e < 3) ? rv[e + 1] : __ldg(regb + t + 4);
                const float dl = rn - rv[e];
                const float dr = rn - rnext;
                reg_sum += 0.5f * (dl * dl + dr * dr);
            }
        }
    }

    // Block reduce four values (np/K as float)
    float v0 = cls_sum, v1 = (float)np, v2 = reg_sum, v3 = (float)K;
    #pragma unroll
    for (int o = 16; o > 0; o >>= 1) {
        v0 += __shfl_down_sync(0xFFFFFFFFu, v0, o);
        v1 += __shfl_down_sync(0xFFFFFFFFu, v1, o);
        v2 += __shfl_down_sync(0xFFFFFFFFu, v2, o);
        v3 += __shfl_down_sync(0xFFFFFFFFu, v3, o);
    }
    __shared__ float sm[4][TPB / 32];
    __shared__ unsigned int s_ticket;
    const int warp = threadIdx.x >> 5;
    const int lane = threadIdx.x & 31;
    if (lane == 0) {
        sm[0][warp] = v0; sm[1][warp] = v1; sm[2][warp] = v2; sm[3][warp] = v3;
    }
    __syncthreads();
    if (threadIdx.x == 0) {
        float s0 = 0.f, s1 = 0.f, s2 = 0.f, s3 = 0.f;
        #pragma unroll
        for (int w = 0; w < TPB / 32; ++w) {
            s0 += sm[0][w]; s1 += sm[1][w]; s2 += sm[2][w]; s3 += sm[3][w];
        }
        float* dst = &g_partial[((size_t)b * CHUNKS + chunk) * 4];
        __stcg(dst + 0, s0);                   // L2-direct, no L1 involvement
        __stcg(dst + 1, s1);
        __stcg(dst + 2, s2);
        __stcg(dst + 3, s3);
        s_ticket = ticket_acq_rel(&g_ticket);  // release: stores above visible first
    }
    __syncthreads();

    if (s_ticket != NBLOCKS - 1) return;

    // ---- Final reduction: this is the last block; all partials are in L2 ----
    {
        const int sb = threadIdx.x;            // sample index, 0..255
        float sc = 0.f, sn = 0.f, sr = 0.f, sk = 0.f;
        #pragma unroll
        for (int ch = 0; ch < CHUNKS; ++ch) {
            const float* p = &g_partial[((size_t)sb * CHUNKS + ch) * 4];
            sc += __ldcg(p + 0);
            sn += __ldcg(p + 1);
            sr += __ldcg(p + 2);
            sk += __ldcg(p + 3);
        }
        float cls_loss = sc / sn * 10.0f;
        float reg_loss = sr / sk * 10.0f;

        #pragma unroll
        for (int o = 16; o > 0; o >>= 1) {
            cls_loss += __shfl_down_sync(0xFFFFFFFFu, cls_loss, o);
            reg_loss += __shfl_down_sync(0xFFFFFFFFu, reg_loss, o);
        }
        __shared__ float sA[TPB / 32], sB[TPB / 32];
        if (lane == 0) { sA[warp] = cls_loss; sB[warp] = reg_loss; }
        __syncthreads();
        if (threadIdx.x == 0) {
            float tc = 0.f, tr = 0.f;
            #pragma unroll
            for (int w = 0; w < TPB / 32; ++w) { tc += sA[w]; tr += sB[w]; }
            out[0] = tc * (1.0f / (float)B_N);
            out[1] = tr * (1.0f / (float)B_N);
            __stcg(&g_ticket, 0u);             // reset for next graph replay
        }
    }
}

extern "C" void kernel_launch(void* const* d_in, const int* in_sizes, int n_in,
                              void* d_out, int out_size) {
    const float* cls = (const float*)d_in[0];  // [B, T, 2]
    const float* reg = (const float*)d_in[1];  // [B, T, 1]
    const float* ann = (const float*)d_in[2];  // [B, 3, T]
    float* out = (float*)d_out;                // [2]

    dim3 grid(CHUNKS, B_N);
    fused_kernel<<<grid, TPB>>>(cls, reg, ann, out);
}

// round 4
// speedup vs baseline: 1.0843x; 1.0753x over previous
#include <cuda_runtime.h>
#include <cstdint>

// Problem shape (fixed by the dataset)
constexpr int B_N    = 256;
constexpr int T_N    = 16384;
constexpr int CHUNKS = 8;                      // chunks per sample -> 2048 blocks
constexpr int TPB    = 256;
constexpr int CHUNK_ELEMS = T_N / CHUNKS;      // 2048 elems per block
constexpr int QUADS_PER_THREAD = CHUNK_ELEMS / 4 / TPB;  // 2
constexpr int NBLOCKS = B_N * CHUNKS;          // 2048

constexpr float EPS_C    = 1e-4f;
// SR / (T * TARGET_FACTOR) = 22050 / (16384*256)
constexpr float INV_CLIP = 22050.0f / (16384.0f * 256.0f);

// Per-(sample,chunk) partials: {cls_sum, num_pos, reg_sum, K}
__device__ float g_partial[NBLOCKS * 4];
__device__ unsigned int g_ticket;  // zero-init; reset by final block each run

__device__ __forceinline__ float cls_term(float c, bool lab) {
    c = fminf(fmaxf(c, EPS_C), 1.0f - EPS_C);
    const float cm = 1.0f - c;
    const float p  = lab ? cm : c;         // focal base
    const float q  = lab ? c  : cm;        // log argument
    const float a  = lab ? 0.25f : 0.75f;
    const float nlg = -__logf(q);
    const float p2 = p * p;
    return (a * (p2 * p2 * p)) * nlg;
}

// acq_rel ticket: release orders prior __stcg stores; acquire covers the
// winner's __ldcg reads. No CCTL.IVALL emitted (unlike __threadfence()).
__device__ __forceinline__ unsigned int ticket_acq_rel(unsigned int* p) {
    unsigned int old;
    asm volatile("atom.acq_rel.gpu.global.add.u32 %0, [%1], 1;"
                 : "=r"(old) : "l"(p) : "memory");
    return old;
}

__global__ __launch_bounds__(TPB, 7) void fused_kernel(
    const float* __restrict__ cls,   // [B, T, 2]
    const float* __restrict__ reg,   // [B, T, 1]
    const float* __restrict__ ann,   // [B, 3, T]
    float* __restrict__ out)         // [2]
{
    const int b     = blockIdx.y;
    const int chunk = blockIdx.x;
    const int tbase = chunk * CHUNK_ELEMS;

    const float* __restrict__ ann0 = ann + (size_t)b * 3 * T_N;
    const float* __restrict__ clsb = cls + (size_t)b * T_N * 2;
    const float* __restrict__ regb = reg + (size_t)b * T_N;

    float cls_sum = 0.0f;
    float reg_sum = 0.0f;
    float np = 0.0f;   // original beat count (classification normalizer)
    float K  = 0.0f;   // fixed-mask count (regression normalizer)

    #pragma unroll
    for (int j = 0; j < QUADS_PER_THREAD; ++j) {
        const int q = threadIdx.x + j * TPB;   // quad index within chunk
        const int t = tbase + q * 4;

        // Six read-once streams: evict-first
        const float4 a0 = __ldcs(reinterpret_cast<const float4*>(ann0 + t));
        const float4 a1 = __ldcs(reinterpret_cast<const float4*>(ann0 + T_N + t));
        const float4 a2 = __ldcs(reinterpret_cast<const float4*>(ann0 + 2 * T_N + t));
        const float4 cA = __ldcs(reinterpret_cast<const float4*>(clsb + 2 * t));
        const float4 cB = __ldcs(reinterpret_cast<const float4*>(clsb + 2 * t + 4));
        const float4 r  = __ldcs(reinterpret_cast<const float4*>(regb + t));

        const float a0v[4] = {a0.x, a0.y, a0.z, a0.w};
        const float a1v[4] = {a1.x, a1.y, a1.z, a1.w};
        const float a2v[4] = {a2.x, a2.y, a2.z, a2.w};
        const float cv[8]  = {cA.x, cA.y, cA.z, cA.w, cB.x, cB.y, cB.z, cB.w};
        const float rv[4]  = {r.x,  r.y,  r.z,  r.w};

        // clamped neighbor index for the e==3 element (only OOB at t+4==T_N)
        const int nidx = (t + 4 < T_N) ? (t + 4) : (T_N - 1);

        #pragma unroll
        for (int e = 0; e < 4; ++e) {
            const bool beat = (a0v[e] != 0.0f);
            const bool down = (a1v[e] != 0.0f);
            np += beat ? 1.0f : 0.0f;
            cls_sum += cls_term(cv[2 * e],     beat && down);
            cls_sum += cls_term(cv[2 * e + 1], beat && !down);

            // UNIFORM regression pass (pos = beat); end-fix applied later
            if (beat) {
                K += 1.0f;
                const float rn    = a2v[e] * INV_CLIP;
                const float rnext = (e < 3) ? rv[e + 1] : __ldg(regb + nidx);
                const float dl = rn - rv[e];
                const float dr = rn - rnext;
                reg_sum = fmaf(0.5f * dl, dl, reg_sum);
                reg_sum = fmaf(0.5f * dr, dr, reg_sum);
            }
        }
    }

    // ---- end-fix correction, one thread per sample (owns last quad) ----
    // Uniform loop treated pos=beat everywhere with rnext clamped to T-1.
    // Fixed semantics: pos[T-2] |= beat[T-1]; pos[T-1] = 0.
    if (chunk == CHUNKS - 1 && threadIdx.x == TPB - 1) {
        const float b2 = __ldg(ann0 + T_N - 2);          // beat[T-2]
        const float b3 = __ldg(ann0 + T_N - 1);          // beat[T-1]
        if (b3 != 0.0f) {
            const float r2  = __ldg(regb + T_N - 2);
            const float r3  = __ldg(regb + T_N - 1);
            const float rn3 = __ldg(ann0 + 3 * T_N - 1) * INV_CLIP;  // ann2[T-1]
            // remove the T-1 term the uniform loop added: (rn3-r3)^2, K--
            const float d3 = rn3 - r3;
            reg_sum -= d3 * d3;
            K -= 1.0f;
            if (b2 == 0.0f) {
                // add the fixed T-2 term, K++
                const float rn2 = __ldg(ann0 + 3 * T_N - 2) * INV_CLIP;
                const float dl = rn2 - r2;
                const float dr = rn2 - r3;
                reg_sum += 0.5f * (dl * dl + dr * dr);
                K += 1.0f;
            }
        }
    }

    // Block reduce four values
    float v0 = cls_sum, v1 = np, v2 = reg_sum, v3 = K;
    #pragma unroll
    for (int o = 16; o > 0; o >>= 1) {
        v0 += __shfl_down_sync(0xFFFFFFFFu, v0, o);
        v1 += __shfl_down_sync(0xFFFFFFFFu, v1, o);
        v2 += __shfl_down_sync(0xFFFFFFFFu, v2, o);
        v3 += __shfl_down_sync(0xFFFFFFFFu, v3, o);
    }
    __shared__ float sm[4][TPB / 32];
    __shared__ unsigned int s_ticket;
    const int warp = threadIdx.x >> 5;
    const int lane = threadIdx.x & 31;
    if (lane == 0) {
        sm[0][warp] = v0; sm[1][warp] = v1; sm[2][warp] = v2; sm[3][warp] = v3;
    }
    __syncthreads();
    if (threadIdx.x == 0) {
        float s0 = 0.f, s1 = 0.f, s2 = 0.f, s3 = 0.f;
        #pragma unroll
        for (int w = 0; w < TPB / 32; ++w) {
            s0 += sm[0][w]; s1 += sm[1][w]; s2 += sm[2][w]; s3 += sm[3][w];
        }
        float* dst = &g_partial[((size_t)b * CHUNKS + chunk) * 4];
        __stcg(dst + 0, s0);                   // L2-direct
        __stcg(dst + 1, s1);
        __stcg(dst + 2, s2);
        __stcg(dst + 3, s3);
        s_ticket = ticket_acq_rel(&g_ticket);  // release: stores visible first
    }
    __syncthreads();

    if (s_ticket != NBLOCKS - 1) return;

    // ---- Final reduction in the last-finishing block ----
    {
        const int sb = threadIdx.x;            // sample index, 0..255
        float sc = 0.f, sn = 0.f, sr = 0.f, sk = 0.f;
        #pragma unroll
        for (int ch = 0; ch < CHUNKS; ++ch) {
            const float* p = &g_partial[((size_t)sb * CHUNKS + ch) * 4];
            sc += __ldcg(p + 0);
            sn += __ldcg(p + 1);
            sr += __ldcg(p + 2);
            sk += __ldcg(p + 3);
        }
        float cls_loss = sc / sn * 10.0f;
        float reg_loss = sr / sk * 10.0f;

        #pragma unroll
        for (int o = 16; o > 0; o >>= 1) {
            cls_loss += __shfl_down_sync(0xFFFFFFFFu, cls_loss, o);
            reg_loss += __shfl_down_sync(0xFFFFFFFFu, reg_loss, o);
        }
        __shared__ float sA[TPB / 32], sB[TPB / 32];
        if (lane == 0) { sA[warp] = cls_loss; sB[warp] = reg_loss; }
        __syncthreads();
        if (threadIdx.x == 0) {
            float tc = 0.f, tr = 0.f;
            #pragma unroll
            for (int w = 0; w < TPB / 32; ++w) { tc += sA[w]; tr += sB[w]; }
            out[0] = tc * (1.0f / (float)B_N);
            out[1] = tr * (1.0f / (float)B_N);
            __stcg(&g_ticket, 0u);             // reset for next graph replay
        }
    }
}

extern "C" void kernel_launch(void* const* d_in, const int* in_sizes, int n_in,
                              void* d_out, int out_size) {
    const float* cls = (const float*)d_in[0];  // [B, T, 2]
    const float* reg = (const float*)d_in[1];  // [B, T, 1]
    const float* ann = (const float*)d_in[2];  // [B, 3, T]
    float* out = (float*)d_out;                // [2]

    dim3 grid(CHUNKS, B_N);
    fused_kernel<<<grid, TPB>>>(cls, reg, ann, out);
}

// round 5
// speedup vs baseline: 1.2000x; 1.1067x over previous
#include <cuda_runtime.h>
#include <cstdint>

constexpr int B_N  = 256;
constexpr int T_N  = 16384;
constexpr int TPB  = 256;
constexpr int CHUNK = 1024;               // elements per pipeline stage
constexpr int CPS  = T_N / CHUNK;         // 16 chunks per sample
constexpr int NCTA = 512;                 // all resident in one wave (~3.5/SM)
constexpr int KPC  = (B_N * CPS) / NCTA;  // 8 chunks per CTA (contiguous, one sample per 2 CTAs)

constexpr float EPS_C    = 1e-4f;
constexpr float INV_CLIP = 22050.0f / (16384.0f * 256.0f);

// SMEM stage layout (floats): a0 | a1 | a2 | rg | cl(2*CHUNK)
constexpr int A0 = 0;
constexpr int A1 = CHUNK;
constexpr int A2 = 2 * CHUNK;
constexpr int RG = 3 * CHUNK;
constexpr int CL = 4 * CHUNK;
constexpr int STAGE_F = 6 * CHUNK;        // 24KB per stage

__device__ float g_partial[NCTA * 4];
__device__ unsigned int g_ticket;         // zero-init; reset by final block

__device__ __forceinline__ float cls_term(float c, bool lab) {
    c = fminf(fmaxf(c, EPS_C), 1.0f - EPS_C);
    const float cm = 1.0f - c;
    const float p  = lab ? cm : c;
    const float q  = lab ? c  : cm;
    const float a  = lab ? 0.25f : 0.75f;
    const float nlg = -__logf(q);
    const float p2 = p * p;
    return (a * (p2 * p2 * p)) * nlg;
}

__device__ __forceinline__ void cp16(float* smem_dst, const float* gsrc) {
    unsigned s = (unsigned)__cvta_generic_to_shared(smem_dst);
    asm volatile("cp.async.cg.shared.global [%0], [%1], 16;" :: "r"(s), "l"(gsrc));
}

__device__ __forceinline__ unsigned ticket_acq_rel(unsigned* p) {
    unsigned old;
    asm volatile("atom.acq_rel.gpu.global.add.u32 %0, [%1], 1;"
                 : "=r"(old) : "l"(p) : "memory");
    return old;
}

__device__ __forceinline__ void issue_stage(
    float* P, const float* cls, const float* reg, const float* ann,
    int gc, int tid)
{
    const int b   = gc / CPS;
    const int cis = gc % CPS;
    const float* ann_b = ann + (size_t)b * 3 * T_N + cis * CHUNK;
    const float* cls_b = cls + (size_t)b * 2 * T_N + cis * 2 * CHUNK;
    const float* reg_b = reg + (size_t)b * T_N + cis * CHUNK;
    cp16(P + A0 + tid * 4, ann_b + tid * 4);                 // beat mask
    cp16(P + A1 + tid * 4, ann_b + T_N + tid * 4);           // downbeat
    cp16(P + A2 + tid * 4, ann_b + 2 * T_N + tid * 4);       // beat times
    cp16(P + RG + tid * 4, reg_b + tid * 4);                 // regressions
    cp16(P + CL + tid * 4, cls_b + tid * 4);                 // cls first half
    cp16(P + CL + CHUNK + tid * 4, cls_b + CHUNK + tid * 4); // cls second half
    asm volatile("cp.async.commit_group;" ::: "memory");
}

__global__ __launch_bounds__(TPB) void fused_kernel(
    const float* __restrict__ cls,   // [B, T, 2]
    const float* __restrict__ reg,   // [B, T, 1]
    const float* __restrict__ ann,   // [B, 3, T]
    float* __restrict__ out)         // [2]
{
    __shared__ float pool[2][STAGE_F];   // 48KB total
    const int c   = blockIdx.x;
    const int tid = threadIdx.x;

    float cls_sum = 0.0f, reg_sum = 0.0f, np = 0.0f, Kc = 0.0f;

    // Prologue: load chunk 0
    issue_stage(pool[0], cls, reg, ann, c * KPC, tid);

    for (int k = 0; k < KPC; ++k) {
        const int gc  = c * KPC + k;
        const int b   = gc / CPS;
        const int cis = gc % CPS;

        if (k + 1 < KPC) {
            issue_stage(pool[(k + 1) & 1], cls, reg, ann, gc + 1, tid);
            asm volatile("cp.async.wait_group 1;" ::: "memory");
        } else {
            asm volatile("cp.async.wait_group 0;" ::: "memory");
        }
        __syncthreads();

        const float* P = pool[k & 1];
        const float4 a0 = *reinterpret_cast<const float4*>(P + A0 + tid * 4);
        const float4 a1 = *reinterpret_cast<const float4*>(P + A1 + tid * 4);
        const float4 a2 = *reinterpret_cast<const float4*>(P + A2 + tid * 4);
        const float4 r  = *reinterpret_cast<const float4*>(P + RG + tid * 4);
        const float4 cA = *reinterpret_cast<const float4*>(P + CL + tid * 8);
        const float4 cB = *reinterpret_cast<const float4*>(P + CL + tid * 8 + 4);

        const float a0v[4] = {a0.x, a0.y, a0.z, a0.w};
        const float a1v[4] = {a1.x, a1.y, a1.z, a1.w};
        const float a2v[4] = {a2.x, a2.y, a2.z, a2.w};
        const float cv[8]  = {cA.x, cA.y, cA.z, cA.w, cB.x, cB.y, cB.z, cB.w};
        const float rv[4]  = {r.x,  r.y,  r.z,  r.w};

        // neighbor for e==3: in-SMEM except for last thread of chunk
        float rnext3;
        if (tid == TPB - 1) {
            const int t0 = cis * CHUNK + tid * 4;
            const int ni = (t0 + 4 < T_N) ? (t0 + 4) : (T_N - 1);
            rnext3 = __ldg(reg + (size_t)b * T_N + ni);
        } else {
            rnext3 = P[RG + tid * 4 + 4];
        }

        #pragma unroll
        for (int e = 0; e < 4; ++e) {
            const bool beat = (a0v[e] != 0.0f);
            const bool down = (a1v[e] != 0.0f);
            np += beat ? 1.0f : 0.0f;
            cls_sum += cls_term(cv[2 * e],     beat && down);
            cls_sum += cls_term(cv[2 * e + 1], beat && !down);

            // uniform regression pass (pos = beat); end-fix applied below
            if (beat) {
                Kc += 1.0f;
                const float rn    = a2v[e] * INV_CLIP;
                const float rnext = (e < 3) ? rv[e + 1] : rnext3;
                const float dl = rn - rv[e];
                const float dr = rn - rnext;
                reg_sum = fmaf(0.5f * dl, dl, reg_sum);
                reg_sum = fmaf(0.5f * dr, dr, reg_sum);
            }
        }

        // end-fix: pos[T-2] |= beat[T-1]; pos[T-1] = 0
        // (uniform pass added (rn3-r3)^2 at T-1 since rnext clamps to r3)
        if (cis == CPS - 1 && tid == TPB - 1) {
            if (a0v[3] != 0.0f) {
                const float rn3 = a2v[3] * INV_CLIP;
                const float d3  = rn3 - rv[3];
                reg_sum -= d3 * d3;
                Kc -= 1.0f;
                if (a0v[2] == 0.0f) {
                    const float rn2 = a2v[2] * INV_CLIP;
                    const float dl = rn2 - rv[2];
                    const float dr = rn2 - rv[3];
                    reg_sum += 0.5f * (dl * dl + dr * dr);
                    Kc += 1.0f;
                }
            }
        }
        __syncthreads();   // buffer k may be overwritten next iteration
    }

    // ---- block reduce 4 accumulators; scratch overlays pool[0] ----
    float v0 = cls_sum, v1 = np, v2 = reg_sum, v3 = Kc;
    #pragma unroll
    for (int o = 16; o > 0; o >>= 1) {
        v0 += __shfl_down_sync(0xFFFFFFFFu, v0, o);
        v1 += __shfl_down_sync(0xFFFFFFFFu, v1, o);
        v2 += __shfl_down_sync(0xFFFFFFFFu, v2, o);
        v3 += __shfl_down_sync(0xFFFFFFFFu, v3, o);
    }
    float* sm = pool[0];                       // [4][8] scratch, tick at [40]
    const int warp = tid >> 5, lane = tid & 31;
    if (lane == 0) {
        sm[0 * 8 + warp] = v0; sm[1 * 8 + warp] = v1;
        sm[2 * 8 + warp] = v2; sm[3 * 8 + warp] = v3;
    }
    __syncthreads();
    if (tid == 0) {
        float s0 = 0.f, s1 = 0.f, s2 = 0.f, s3 = 0.f;
        #pragma unroll
        for (int w = 0; w < 8; ++w) {
            s0 += sm[0 * 8 + w]; s1 += sm[1 * 8 + w];
            s2 += sm[2 * 8 + w]; s3 += sm[3 * 8 + w];
        }
        float* dst = &g_partial[(size_t)c * 4];
        __stcg(dst + 0, s0); __stcg(dst + 1, s1);
        __stcg(dst + 2, s2); __stcg(dst + 3, s3);
        reinterpret_cast<unsigned*>(sm)[40] = ticket_acq_rel(&g_ticket);
    }
    __syncthreads();
    const unsigned tick = reinterpret_cast<unsigned*>(sm)[40];
    if (tick != NCTA - 1) return;

    // ---- final reduction in last-finishing CTA ----
    {
        const int sb = tid;                    // sample index 0..255
        float sc = 0.f, sn = 0.f, sr = 0.f, sk = 0.f;
        #pragma unroll
        for (int h = 0; h < 2; ++h) {          // two CTAs per sample
            const float* p = &g_partial[((size_t)sb * 2 + h) * 4];
            sc += __ldcg(p + 0); sn += __ldcg(p + 1);
            sr += __ldcg(p + 2); sk += __ldcg(p + 3);
        }
        float cl = sc / sn * 10.0f;
        float rl = sr / sk * 10.0f;
        #pragma unroll
        for (int o = 16; o > 0; o >>= 1) {
            cl += __shfl_down_sync(0xFFFFFFFFu, cl, o);
            rl += __shfl_down_sync(0xFFFFFFFFu, rl, o);
        }
        if (lane == 0) { sm[48 + warp] = cl; sm[56 + warp] = rl; }
        __syncthreads();
        if (tid == 0) {
            float tc = 0.f, tr = 0.f;
            #pragma unroll
            for (int w = 0; w < 8; ++w) { tc += sm[48 + w]; tr += sm[56 + w]; }
            out[0] = tc * (1.0f / (float)B_N);
            out[1] = tr * (1.0f / (float)B_N);
            __stcg(&g_ticket, 0u);             // reset for next replay
        }
    }
}

extern "C" void kernel_launch(void* const* d_in, const int* in_sizes, int n_in,
                              void* d_out, int out_size) {
    const float* cls = (const float*)d_in[0];  // [B, T, 2]
    const float* reg = (const float*)d_in[1];  // [B, T, 1]
    const float* ann = (const float*)d_in[2];  // [B, 3, T]
    float* out = (float*)d_out;                // [2]

    fused_kernel<<<NCTA, TPB>>>(cls, reg, ann, out);
}